// round 3
// baseline (speedup 1.0000x reference)
#include <cuda_runtime.h>
#include <cuda_bf16.h>

// Problem constants
#define NN     10000
#define EE     40000
#define GG     128
#define ATOMF  32
#define EDGEF  32
#define STATEF 16
#define DD     48          // ATOM + STATE
#define NPLANE 33          // 32 e-dims + 1 bias plane
#define CDIM   (NPLANE*DD) // 1584

// ---------------- scratch (no allocation allowed) ----------------
__device__ __align__(16) float g_a[NN*ATOMF];      // current atom features
__device__ __align__(16) float g_e[EE*EDGEF];      // current edge features
__device__ __align__(16) float g_s[GG*STATEF];     // current state attrs
__device__ __align__(16) float g_agg[NN*DD];       // segment-summed messages
__device__ __align__(16) float g_asum[GG*ATOMF];
__device__ __align__(16) float g_esum[GG*EDGEF];
__device__ __align__(16) float g_Kt[CDIM*DD];      // K'[(k*48+j)*48 + i] = kernel[k][i*48+j]; plane 32 = bias

__device__ __forceinline__ float sigm(float x) { return 1.0f / (1.0f + __expf(-x)); }

// ---------------- init: copy state + build transposed kernel ----------------
__global__ void k_init(const float* __restrict__ a0, const float* __restrict__ e0,
                       const float* __restrict__ s0, const float* __restrict__ Kmat,
                       const float* __restrict__ bias) {
    int i = blockIdx.x * blockDim.x + threadIdx.x;
    const int na = NN*ATOMF, ne = EE*EDGEF, ns = GG*STATEF, nk = CDIM*DD;
    if (i < na) { g_a[i] = a0[i]; return; }
    i -= na;
    if (i < ne) { g_e[i] = e0[i]; return; }
    i -= ne;
    if (i < ns) { g_s[i] = s0[i]; return; }
    i -= ns;
    if (i < nk) {
        int c = i / DD, col = i % DD;
        if (c < 32*DD) { int k = c / DD, j = c % DD; g_Kt[i] = Kmat[k*(DD*DD) + col*DD + j]; }
        else           { int j = c - 32*DD;          g_Kt[i] = bias[col*DD + j]; }
    }
}

// ---------------- zero accumulators ----------------
__global__ void k_zero() {
    int i = blockIdx.x * blockDim.x + threadIdx.x;
    if (i < NN*DD) { g_agg[i] = 0.f; return; }
    i -= NN*DD;
    if (i < GG*ATOMF) { g_asum[i] = 0.f; return; }
    i -= GG*ATOMF;
    if (i < GG*EDGEF) g_esum[i] = 0.f;
}

// ---------------- edge GRU: e = GRU([a[src],a[dst],s[bgi],e], e) ----------------
// 256 threads = 8 warps; each warp processes 4 edges concurrently (weight LDS amortized).
// Fused epilogue: run-length-combined atomic accumulation of new e into g_esum
// (bgi sorted -> ~1 atomic per 4 edges per lane).
__global__ void k_edge_gru(const float* __restrict__ We, const float* __restrict__ Ue,
                           const float* __restrict__ bein, const float* __restrict__ berec,
                           const int* __restrict__ pair, const int* __restrict__ bgi) {
    extern __shared__ float sm[];
    float* sW  = sm;                       // 112*96 = 10752
    float* sU  = sm + 112*96;              // 32*96  = 3072
    float* sEC = sm + 112*96 + 32*96;      // 8 warps * 4 edges * 112 = 3584
    int tid = threadIdx.x;
    for (int i = tid; i < 112*96; i += 256) sW[i] = We[i];
    for (int i = tid; i < 32*96;  i += 256) sU[i] = Ue[i];
    __syncthreads();

    int warp = tid >> 5, lane = tid & 31;
    int ebase = blockIdx.x * 32 + warp * 4;
    float* ec = sEC + warp * (4*112);

    int gb[4];
#pragma unroll
    for (int t = 0; t < 4; t++) {
        int eidx = ebase + t;
        int src = pair[2*eidx], dst = pair[2*eidx+1];
        gb[t] = bgi[eidx];
        ec[t*112 + lane]      = g_a[src*ATOMF + lane];
        ec[t*112 + 32 + lane] = g_a[dst*ATOMF + lane];
        if (lane < 16) ec[t*112 + 64 + lane] = g_s[gb[t]*STATEF + lane];
        ec[t*112 + 80 + lane] = g_e[eidx*EDGEF + lane];
    }
    __syncwarp();

    float bz = bein[lane], br = bein[32+lane], bh = bein[64+lane];
    float cz = berec[lane], cr = berec[32+lane], ch = berec[64+lane];
    float xz[4], xr[4], xh[4], hz[4], hr[4], hh[4];
#pragma unroll
    for (int t = 0; t < 4; t++) { xz[t]=bz; xr[t]=br; xh[t]=bh; hz[t]=cz; hr[t]=cr; hh[t]=ch; }

    for (int c = 0; c < 112; c++) {
        float w0 = sW[c*96 + lane], w1 = sW[c*96 + 32 + lane], w2 = sW[c*96 + 64 + lane];
#pragma unroll
        for (int t = 0; t < 4; t++) {
            float v = ec[t*112 + c];
            xz[t] += v*w0; xr[t] += v*w1; xh[t] += v*w2;
        }
    }
    for (int c = 0; c < 32; c++) {
        float u0 = sU[c*96 + lane], u1 = sU[c*96 + 32 + lane], u2 = sU[c*96 + 64 + lane];
#pragma unroll
        for (int t = 0; t < 4; t++) {
            float v = ec[t*112 + 80 + c];
            hz[t] += v*u0; hr[t] += v*u1; hh[t] += v*u2;
        }
    }
    float val[4];
#pragma unroll
    for (int t = 0; t < 4; t++) {
        int eidx = ebase + t;
        float h = ec[t*112 + 80 + lane];
        float z = sigm(xz[t] + hz[t]);
        float r = sigm(xr[t] + hr[t]);
        float hc = tanhf(xh[t] + r*hh[t]);
        val[t] = z*h + (1.f - z)*hc;
        g_e[eidx*EDGEF + lane] = val[t];
    }
    // fused e_sum scatter (bgi sorted -> run-length combine)
    float run = val[0];
    int cur = gb[0];
#pragma unroll
    for (int t = 1; t < 4; t++) {
        if (gb[t] == cur) run += val[t];
        else { atomicAdd(&g_esum[cur*EDGEF + lane], run); cur = gb[t]; run = val[t]; }
    }
    atomicAdd(&g_esum[cur*EDGEF + lane], run);
}

// ---------------- einsum + segment scatter ----------------
// t[edge,i] = sum_k e_ext[k] * (sum_j K'[k*48+j][i] * x[edge,j]),  x = [a[dst], s[agi[dst]]]
// Block: 64 edges x 48 cols, 256 threads, thread = 4 edges x 3 cols.
#define TE 64
__global__ void k_einsum(const int* __restrict__ pair, const int* __restrict__ agi) {
    __shared__ __align__(16) float Ks[2*DD*DD];   // 2 planes staged: 4608 floats
    __shared__ float xs[TE*49];                   // x rows, padded stride
    __shared__ float es[TE*33];                   // e rows + 1.0 bias coeff
    __shared__ int   srcs[TE];
    int tid = threadIdx.x;
    int e0 = blockIdx.x * TE;

    for (int idx = tid; idx < TE*DD; idx += 256) {
        int le = idx / DD, j = idx % DD;
        int ge = e0 + le;
        int dst = pair[2*ge + 1];
        xs[le*49 + j] = (j < ATOMF) ? g_a[dst*ATOMF + j] : g_s[agi[dst]*STATEF + (j - ATOMF)];
    }
    for (int idx = tid; idx < TE*33; idx += 256) {
        int le = idx / 33, k = idx % 33;
        es[le*33 + k] = (k < 32) ? g_e[(e0+le)*EDGEF + k] : 1.0f;
    }
    if (tid < TE) srcs[tid] = pair[2*(e0 + tid)];

    int tx = tid & 15, ty = tid >> 4;
    float acc[4][3];
#pragma unroll
    for (int t = 0; t < 4; t++) { acc[t][0]=0.f; acc[t][1]=0.f; acc[t][2]=0.f; }

    for (int p0 = 0; p0 < NPLANE; p0 += 2) {
        int np = (NPLANE - p0) >= 2 ? 2 : 1;
        __syncthreads();                           // protect Ks from previous chunk readers
        {
            int nf4 = (np * DD * DD) >> 2;
            float4*       d4 = (float4*)Ks;
            const float4* s4 = (const float4*)(g_Kt + p0*DD*DD);
            for (int idx = tid; idx < nf4; idx += 256) d4[idx] = s4[idx];
        }
        __syncthreads();
#pragma unroll
        for (int p = 0; p < 2; p++) {
            if (p >= np) break;
            int k = p0 + p;
            float ez[4];
#pragma unroll
            for (int t = 0; t < 4; t++) ez[t] = es[(ty + 16*t)*33 + k];
            float u[4][3];
#pragma unroll
            for (int t = 0; t < 4; t++) { u[t][0]=0.f; u[t][1]=0.f; u[t][2]=0.f; }
            const float* Kp = Ks + p*DD*DD;
#pragma unroll
            for (int j = 0; j < DD; j++) {
                float k0 = Kp[j*DD + tx], k1 = Kp[j*DD + 16 + tx], k2 = Kp[j*DD + 32 + tx];
#pragma unroll
                for (int t = 0; t < 4; t++) {
                    float xv = xs[(ty + 16*t)*49 + j];
                    u[t][0] += xv*k0; u[t][1] += xv*k1; u[t][2] += xv*k2;
                }
            }
#pragma unroll
            for (int t = 0; t < 4; t++) {
                acc[t][0] += ez[t]*u[t][0];
                acc[t][1] += ez[t]*u[t][1];
                acc[t][2] += ez[t]*u[t][2];
            }
        }
    }
    __syncthreads();
    // stage t-tile into xs (reuse), then segmented reduction over sorted src
#pragma unroll
    for (int t = 0; t < 4; t++) {
        xs[(ty + 16*t)*49 + tx]      = acc[t][0];
        xs[(ty + 16*t)*49 + 16 + tx] = acc[t][1];
        xs[(ty + 16*t)*49 + 32 + tx] = acc[t][2];
    }
    __syncthreads();
    if (tid < DD) {
        int col = tid;
        float run = 0.f;
        int cur = srcs[0];
        for (int le = 0; le < TE; le++) {
            int sv = srcs[le];
            if (sv != cur) { atomicAdd(&g_agg[cur*DD + col], run); run = 0.f; cur = sv; }
            run += xs[le*49 + col];
        }
        atomicAdd(&g_agg[cur*DD + col], run);
    }
}

// ---------------- node GRU: a = GRU(agg, a); fused a_sum scatter ----------------
__global__ void k_node_gru(const float* __restrict__ Wn, const float* __restrict__ Un,
                           const float* __restrict__ bnin, const float* __restrict__ bnrec,
                           const int* __restrict__ agi) {
    __shared__ float sW[48*96];      // 4608
    __shared__ float sU[32*96];      // 3072
    __shared__ float sX[8*4*48];     // x rows
    __shared__ float sH[8*4*32];     // h rows
    int tid = threadIdx.x;
    for (int i = tid; i < 48*96; i += 256) sW[i] = Wn[i];
    for (int i = tid; i < 32*96; i += 256) sU[i] = Un[i];
    __syncthreads();

    int warp = tid >> 5, lane = tid & 31;
    int nbase = blockIdx.x * 32 + warp * 4;
    float* xb = sX + warp * (4*48);
    float* hb = sH + warp * (4*32);
    bool ok[4];
    int ga[4];
#pragma unroll
    for (int t = 0; t < 4; t++) {
        int n = nbase + t;
        ok[t] = (n < NN);
        ga[t] = -1;
        if (ok[t]) {
            ga[t] = agi[n];
            xb[t*48 + lane] = g_agg[n*DD + lane];
            if (lane < 16) xb[t*48 + 32 + lane] = g_agg[n*DD + 32 + lane];
            hb[t*32 + lane] = g_a[n*ATOMF + lane];
        }
    }
    __syncwarp();

    float bz = bnin[lane], br = bnin[32+lane], bh = bnin[64+lane];
    float cz = bnrec[lane], cr = bnrec[32+lane], ch = bnrec[64+lane];
    float xz[4], xr[4], xh[4], hz[4], hr[4], hh[4];
#pragma unroll
    for (int t = 0; t < 4; t++) { xz[t]=bz; xr[t]=br; xh[t]=bh; hz[t]=cz; hr[t]=cr; hh[t]=ch; }

    for (int c = 0; c < 48; c++) {
        float w0 = sW[c*96 + lane], w1 = sW[c*96 + 32 + lane], w2 = sW[c*96 + 64 + lane];
#pragma unroll
        for (int t = 0; t < 4; t++) {
            float v = xb[t*48 + c];
            xz[t] += v*w0; xr[t] += v*w1; xh[t] += v*w2;
        }
    }
    for (int c = 0; c < 32; c++) {
        float u0 = sU[c*96 + lane], u1 = sU[c*96 + 32 + lane], u2 = sU[c*96 + 64 + lane];
#pragma unroll
        for (int t = 0; t < 4; t++) {
            float v = hb[t*32 + c];
            hz[t] += v*u0; hr[t] += v*u1; hh[t] += v*u2;
        }
    }
    float val[4];
#pragma unroll
    for (int t = 0; t < 4; t++) {
        val[t] = 0.f;
        if (!ok[t]) continue;
        int n = nbase + t;
        float h = hb[t*32 + lane];
        float z = sigm(xz[t] + hz[t]);
        float r = sigm(xr[t] + hr[t]);
        float hc = tanhf(xh[t] + r*hh[t]);
        val[t] = z*h + (1.f - z)*hc;
        g_a[n*ATOMF + lane] = val[t];
    }
    // fused a_sum scatter (agi sorted -> run-length combine)
    int cur = -1;
    float run = 0.f;
#pragma unroll
    for (int t = 0; t < 4; t++) {
        if (!ok[t]) continue;
        if (ga[t] == cur) run += val[t];
        else {
            if (cur >= 0) atomicAdd(&g_asum[cur*ATOMF + lane], run);
            cur = ga[t]; run = val[t];
        }
    }
    if (cur >= 0) atomicAdd(&g_asum[cur*ATOMF + lane], run);
}

// ---------------- state GRU: s = GRU([a_sum, e_sum, s], s) ----------------
// 128 threads/block: 8 graphs, 16 cols each
__global__ void k_state_gru(const float* __restrict__ Ws, const float* __restrict__ Us,
                            const float* __restrict__ bsin, const float* __restrict__ bsrec) {
    int tid = threadIdx.x;
    int g = blockIdx.x * 8 + (tid >> 4);
    int j = tid & 15;
    float xz = bsin[j], xr = bsin[16+j], xh = bsin[32+j];
    float hz = bsrec[j], hr = bsrec[16+j], hh = bsrec[32+j];
    for (int c = 0; c < 80; c++) {
        float v = (c < 32) ? g_asum[g*ATOMF + c]
                : (c < 64) ? g_esum[g*EDGEF + (c-32)]
                           : g_s[g*STATEF + (c-64)];
        xz += v*Ws[c*48 + j]; xr += v*Ws[c*48 + 16 + j]; xh += v*Ws[c*48 + 32 + j];
    }
    float h = g_s[g*STATEF + j];
    for (int c = 0; c < 16; c++) {
        float v = g_s[g*STATEF + c];
        hz += v*Us[c*48 + j]; hr += v*Us[c*48 + 16 + j]; hh += v*Us[c*48 + 32 + j];
    }
    float z = sigm(xz + hz);
    float r = sigm(xr + hr);
    float hc = tanhf(xh + r*hh);
    float out = z*h + (1.f - z)*hc;
    __syncthreads();            // all reads of g_s for this block's graphs complete
    g_s[g*STATEF + j] = out;
}

// ---------------- writeout: (a, e, s) flattened ----------------
__global__ void k_out(float* __restrict__ out) {
    int i = blockIdx.x * blockDim.x + threadIdx.x;
    const int na = NN*ATOMF, ne = EE*EDGEF, ns = GG*STATEF;
    if (i < na) { out[i] = g_a[i]; return; }
    i -= na;
    if (i < ne) { out[NN*ATOMF + i] = g_e[i]; return; }
    i -= ne;
    if (i < ns) out[NN*ATOMF + EE*EDGEF + i] = g_s[i];
}

// ---------------- launch ----------------
extern "C" void kernel_launch(void* const* d_in, const int* in_sizes, int n_in,
                              void* d_out, int out_size) {
    const float* a0    = (const float*)d_in[0];
    const float* e0    = (const float*)d_in[1];
    const float* s0    = (const float*)d_in[2];
    const int*   pair  = (const int*)d_in[3];
    const int*   agi   = (const int*)d_in[4];
    const int*   bgi   = (const int*)d_in[5];
    const float* Kmat  = (const float*)d_in[6];
    const float* bias  = (const float*)d_in[7];
    const float* We    = (const float*)d_in[8];
    const float* Ue    = (const float*)d_in[9];
    const float* bein  = (const float*)d_in[10];
    const float* berec = (const float*)d_in[11];
    const float* Wn    = (const float*)d_in[12];
    const float* Un    = (const float*)d_in[13];
    const float* bnin  = (const float*)d_in[14];
    const float* bnrec = (const float*)d_in[15];
    const float* Ws    = (const float*)d_in[16];
    const float* Us    = (const float*)d_in[17];
    const float* bsin  = (const float*)d_in[18];
    const float* bsrec = (const float*)d_in[19];

    const int eg_smem = (112*96 + 32*96 + 8*4*112) * (int)sizeof(float);  // 69632 B
    cudaFuncSetAttribute(k_edge_gru, cudaFuncAttributeMaxDynamicSharedMemorySize, eg_smem);

    int initN = NN*ATOMF + EE*EDGEF + GG*STATEF + CDIM*DD;
    k_init<<<(initN + 255)/256, 256>>>(a0, e0, s0, Kmat, bias);

    for (int step = 0; step < 2; step++) {
        int zN = NN*DD + GG*ATOMF + GG*EDGEF;
        k_zero<<<(zN + 255)/256, 256>>>();
        k_edge_gru<<<EE/32, 256, eg_smem>>>(We, Ue, bein, berec, pair, bgi);
        k_einsum<<<EE/TE, 256>>>(pair, agi);
        k_node_gru<<<(NN + 31)/32, 256>>>(Wn, Un, bnin, bnrec, agi);
        k_state_gru<<<GG/8, 128>>>(Ws, Us, bsin, bsrec);
    }

    int oN = NN*ATOMF + EE*EDGEF + GG*STATEF;
    k_out<<<(oN + 255)/256, 256>>>((float*)d_out);
}

// round 11
// speedup vs baseline: 1.0356x; 1.0356x over previous
#include <cuda_runtime.h>
#include <cuda_bf16.h>

// Problem constants
#define NN     10000
#define EE     40000
#define GG     128
#define ATOMF  32
#define EDGEF  32
#define STATEF 16
#define DD     48          // ATOM + STATE
#define NPLANE 33          // 32 e-dims + 1 bias plane
#define CDIM   (NPLANE*DD) // 1584

// ---------------- scratch (no allocation allowed) ----------------
__device__ __align__(16) float g_a[NN*ATOMF];      // current atom features
__device__ __align__(16) float g_e[EE*EDGEF];      // current edge features
__device__ __align__(16) float g_s[GG*STATEF];     // current state attrs
__device__ __align__(16) float g_agg[NN*DD];       // segment-summed messages
__device__ __align__(16) float g_asum[GG*ATOMF];
__device__ __align__(16) float g_esum[GG*EDGEF];
__device__ __align__(16) float g_Kt[CDIM*DD];      // K'[(k*48+j)*48 + i] = kernel[k][i*48+j]; plane 32 = bias

__device__ __forceinline__ float sigm(float x) { return 1.0f / (1.0f + __expf(-x)); }

// ---------------- init: copy state + build transposed kernel ----------------
__global__ void k_init(const float* __restrict__ a0, const float* __restrict__ e0,
                       const float* __restrict__ s0, const float* __restrict__ Kmat,
                       const float* __restrict__ bias) {
    int i = blockIdx.x * blockDim.x + threadIdx.x;
    const int na = NN*ATOMF, ne = EE*EDGEF, ns = GG*STATEF, nk = CDIM*DD;
    if (i < na) { g_a[i] = a0[i]; return; }
    i -= na;
    if (i < ne) { g_e[i] = e0[i]; return; }
    i -= ne;
    if (i < ns) { g_s[i] = s0[i]; return; }
    i -= ns;
    if (i < nk) {
        int c = i / DD, col = i % DD;
        if (c < 32*DD) { int k = c / DD, j = c % DD; g_Kt[i] = Kmat[k*(DD*DD) + col*DD + j]; }
        else           { int j = c - 32*DD;          g_Kt[i] = bias[col*DD + j]; }
    }
}

// ---------------- zero accumulators ----------------
__global__ void k_zero() {
    int i = blockIdx.x * blockDim.x + threadIdx.x;
    if (i < NN*DD) { g_agg[i] = 0.f; return; }
    i -= NN*DD;
    if (i < GG*ATOMF) { g_asum[i] = 0.f; return; }
    i -= GG*ATOMF;
    if (i < GG*EDGEF) g_esum[i] = 0.f;
}

// ---------------- edge GRU: e = GRU([a[src],a[dst],s[bgi],e], e) ----------------
// 256 threads = 8 warps; each warp processes 4 edges concurrently (weight LDS amortized).
// Fused epilogue: run-length-combined atomic accumulation of new e into g_esum.
__global__ void __launch_bounds__(256, 2)
k_edge_gru(const float* __restrict__ We, const float* __restrict__ Ue,
           const float* __restrict__ bein, const float* __restrict__ berec,
           const int* __restrict__ pair, const int* __restrict__ bgi) {
    extern __shared__ float sm[];
    float* sW  = sm;                       // 112*96 = 10752
    float* sU  = sm + 112*96;              // 32*96  = 3072
    float* sEC = sm + 112*96 + 32*96;      // 8 warps * 4 edges * 112 = 3584
    int tid = threadIdx.x;
    for (int i = tid; i < 112*96; i += 256) sW[i] = We[i];
    for (int i = tid; i < 32*96;  i += 256) sU[i] = Ue[i];
    __syncthreads();

    int warp = tid >> 5, lane = tid & 31;
    int ebase = blockIdx.x * 32 + warp * 4;
    float* ec = sEC + warp * (4*112);

    int gb[4];
#pragma unroll
    for (int t = 0; t < 4; t++) {
        int eidx = ebase + t;
        int src = pair[2*eidx], dst = pair[2*eidx+1];
        gb[t] = bgi[eidx];
        ec[t*112 + lane]      = g_a[src*ATOMF + lane];
        ec[t*112 + 32 + lane] = g_a[dst*ATOMF + lane];
        if (lane < 16) ec[t*112 + 64 + lane] = g_s[gb[t]*STATEF + lane];
        ec[t*112 + 80 + lane] = g_e[eidx*EDGEF + lane];
    }
    __syncwarp();

    float bz = bein[lane], br = bein[32+lane], bh = bein[64+lane];
    float cz = berec[lane], cr = berec[32+lane], ch = berec[64+lane];
    float xz[4], xr[4], xh[4], hz[4], hr[4], hh[4];
#pragma unroll
    for (int t = 0; t < 4; t++) { xz[t]=bz; xr[t]=br; xh[t]=bh; hz[t]=cz; hr[t]=cr; hh[t]=ch; }

#pragma unroll 8
    for (int c = 0; c < 112; c++) {
        float w0 = sW[c*96 + lane], w1 = sW[c*96 + 32 + lane], w2 = sW[c*96 + 64 + lane];
#pragma unroll
        for (int t = 0; t < 4; t++) {
            float v = ec[t*112 + c];
            xz[t] += v*w0; xr[t] += v*w1; xh[t] += v*w2;
        }
    }
#pragma unroll 8
    for (int c = 0; c < 32; c++) {
        float u0 = sU[c*96 + lane], u1 = sU[c*96 + 32 + lane], u2 = sU[c*96 + 64 + lane];
#pragma unroll
        for (int t = 0; t < 4; t++) {
            float v = ec[t*112 + 80 + c];
            hz[t] += v*u0; hr[t] += v*u1; hh[t] += v*u2;
        }
    }
    float val[4];
#pragma unroll
    for (int t = 0; t < 4; t++) {
        int eidx = ebase + t;
        float h = ec[t*112 + 80 + lane];
        float z = sigm(xz[t] + hz[t]);
        float r = sigm(xr[t] + hr[t]);
        float hc = tanhf(xh[t] + r*hh[t]);
        val[t] = z*h + (1.f - z)*hc;
        g_e[eidx*EDGEF + lane] = val[t];
    }
    // fused e_sum scatter (bgi sorted -> run-length combine)
    float run = val[0];
    int cur = gb[0];
#pragma unroll
    for (int t = 1; t < 4; t++) {
        if (gb[t] == cur) run += val[t];
        else { atomicAdd(&g_esum[cur*EDGEF + lane], run); cur = gb[t]; run = val[t]; }
    }
    atomicAdd(&g_esum[cur*EDGEF + lane], run);
}

// ---------------- einsum + segment scatter ----------------
// t[edge,i] = sum_k e_ext[k] * (sum_j K'[k*48+j][i] * x[edge,j]),  x = [a[dst], s[agi[dst]]]
// Block: 64 edges x 48 cols, 256 threads, thread = 4 edges x 3 cols.
// launch_bounds(256,2): cap regs at 128 so 2 blocks/SM (R3 had regs=229 -> occ 12.3%).
#define TE 64
__global__ void __launch_bounds__(256, 2)
k_einsum(const int* __restrict__ pair, const int* __restrict__ agi) {
    __shared__ __align__(16) float Ks[2*DD*DD];   // 2 planes staged: 4608 floats
    __shared__ float xs[TE*49];                   // x rows, padded stride
    __shared__ float es[TE*33];                   // e rows + 1.0 bias coeff
    __shared__ int   srcs[TE];
    int tid = threadIdx.x;
    int e0 = blockIdx.x * TE;

    for (int idx = tid; idx < TE*DD; idx += 256) {
        int le = idx / DD, j = idx % DD;
        int ge = e0 + le;
        int dst = pair[2*ge + 1];
        xs[le*49 + j] = (j < ATOMF) ? g_a[dst*ATOMF + j] : g_s[agi[dst]*STATEF + (j - ATOMF)];
    }
    for (int idx = tid; idx < TE*33; idx += 256) {
        int le = idx / 33, k = idx % 33;
        es[le*33 + k] = (k < 32) ? g_e[(e0+le)*EDGEF + k] : 1.0f;
    }
    if (tid < TE) srcs[tid] = pair[2*(e0 + tid)];

    int tx = tid & 15, ty = tid >> 4;
    float acc[4][3];
#pragma unroll
    for (int t = 0; t < 4; t++) { acc[t][0]=0.f; acc[t][1]=0.f; acc[t][2]=0.f; }

    for (int p0 = 0; p0 < NPLANE; p0 += 2) {
        int np = (NPLANE - p0) >= 2 ? 2 : 1;
        __syncthreads();                           // protect Ks from previous chunk readers
        {
            int nf4 = (np * DD * DD) >> 2;
            float4*       d4 = (float4*)Ks;
            const float4* s4 = (const float4*)(g_Kt + p0*DD*DD);
            for (int idx = tid; idx < nf4; idx += 256) d4[idx] = s4[idx];
        }
        __syncthreads();
#pragma unroll 1
        for (int p = 0; p < np; p++) {
            int k = p0 + p;
            float ez[4];
#pragma unroll
            for (int t = 0; t < 4; t++) ez[t] = es[(ty + 16*t)*33 + k];
            float u[4][3];
#pragma unroll
            for (int t = 0; t < 4; t++) { u[t][0]=0.f; u[t][1]=0.f; u[t][2]=0.f; }
            const float* Kp = Ks + p*DD*DD;
#pragma unroll 12
            for (int j = 0; j < DD; j++) {
                float k0 = Kp[j*DD + tx], k1 = Kp[j*DD + 16 + tx], k2 = Kp[j*DD + 32 + tx];
#pragma unroll
                for (int t = 0; t < 4; t++) {
                    float xv = xs[(ty + 16*t)*49 + j];
                    u[t][0] += xv*k0; u[t][1] += xv*k1; u[t][2] += xv*k2;
                }
            }
#pragma unroll
            for (int t = 0; t < 4; t++) {
                acc[t][0] += ez[t]*u[t][0];
                acc[t][1] += ez[t]*u[t][1];
                acc[t][2] += ez[t]*u[t][2];
            }
        }
    }
    __syncthreads();
    // stage t-tile into xs (reuse), then segmented reduction over sorted src
#pragma unroll
    for (int t = 0; t < 4; t++) {
        xs[(ty + 16*t)*49 + tx]      = acc[t][0];
        xs[(ty + 16*t)*49 + 16 + tx] = acc[t][1];
        xs[(ty + 16*t)*49 + 32 + tx] = acc[t][2];
    }
    __syncthreads();
    if (tid < DD) {
        int col = tid;
        float run = 0.f;
        int cur = srcs[0];
        for (int le = 0; le < TE; le++) {
            int sv = srcs[le];
            if (sv != cur) { atomicAdd(&g_agg[cur*DD + col], run); run = 0.f; cur = sv; }
            run += xs[le*49 + col];
        }
        atomicAdd(&g_agg[cur*DD + col], run);
    }
}

// ---------------- node GRU: a = GRU(agg, a); fused a_sum scatter ----------------
__global__ void __launch_bounds__(256, 2)
k_node_gru(const float* __restrict__ Wn, const float* __restrict__ Un,
           const float* __restrict__ bnin, const float* __restrict__ bnrec,
           const int* __restrict__ agi) {
    __shared__ float sW[48*96];      // 4608
    __shared__ float sU[32*96];      // 3072
    __shared__ float sX[8*4*48];     // x rows
    __shared__ float sH[8*4*32];     // h rows
    int tid = threadIdx.x;
    for (int i = tid; i < 48*96; i += 256) sW[i] = Wn[i];
    for (int i = tid; i < 32*96; i += 256) sU[i] = Un[i];
    __syncthreads();

    int warp = tid >> 5, lane = tid & 31;
    int nbase = blockIdx.x * 32 + warp * 4;
    float* xb = sX + warp * (4*48);
    float* hb = sH + warp * (4*32);
    bool ok[4];
    int ga[4];
#pragma unroll
    for (int t = 0; t < 4; t++) {
        int n = nbase + t;
        ok[t] = (n < NN);
        ga[t] = -1;
        if (ok[t]) {
            ga[t] = agi[n];
            xb[t*48 + lane] = g_agg[n*DD + lane];
            if (lane < 16) xb[t*48 + 32 + lane] = g_agg[n*DD + 32 + lane];
            hb[t*32 + lane] = g_a[n*ATOMF + lane];
        }
    }
    __syncwarp();

    float bz = bnin[lane], br = bnin[32+lane], bh = bnin[64+lane];
    float cz = bnrec[lane], cr = bnrec[32+lane], ch = bnrec[64+lane];
    float xz[4], xr[4], xh[4], hz[4], hr[4], hh[4];
#pragma unroll
    for (int t = 0; t < 4; t++) { xz[t]=bz; xr[t]=br; xh[t]=bh; hz[t]=cz; hr[t]=cr; hh[t]=ch; }

#pragma unroll 8
    for (int c = 0; c < 48; c++) {
        float w0 = sW[c*96 + lane], w1 = sW[c*96 + 32 + lane], w2 = sW[c*96 + 64 + lane];
#pragma unroll
        for (int t = 0; t < 4; t++) {
            float v = xb[t*48 + c];
            xz[t] += v*w0; xr[t] += v*w1; xh[t] += v*w2;
        }
    }
#pragma unroll 8
    for (int c = 0; c < 32; c++) {
        float u0 = sU[c*96 + lane], u1 = sU[c*96 + 32 + lane], u2 = sU[c*96 + 64 + lane];
#pragma unroll
        for (int t = 0; t < 4; t++) {
            float v = hb[t*32 + c];
            hz[t] += v*u0; hr[t] += v*u1; hh[t] += v*u2;
        }
    }
    float val[4];
#pragma unroll
    for (int t = 0; t < 4; t++) {
        val[t] = 0.f;
        if (!ok[t]) continue;
        int n = nbase + t;
        float h = hb[t*32 + lane];
        float z = sigm(xz[t] + hz[t]);
        float r = sigm(xr[t] + hr[t]);
        float hc = tanhf(xh[t] + r*hh[t]);
        val[t] = z*h + (1.f - z)*hc;
        g_a[n*ATOMF + lane] = val[t];
    }
    // fused a_sum scatter (agi sorted -> run-length combine)
    int cur = -1;
    float run = 0.f;
#pragma unroll
    for (int t = 0; t < 4; t++) {
        if (!ok[t]) continue;
        if (ga[t] == cur) run += val[t];
        else {
            if (cur >= 0) atomicAdd(&g_asum[cur*ATOMF + lane], run);
            cur = ga[t]; run = val[t];
        }
    }
    if (cur >= 0) atomicAdd(&g_asum[cur*ATOMF + lane], run);
}

// ---------------- state GRU: s = GRU([a_sum, e_sum, s], s) ----------------
// 128 threads/block: 8 graphs, 16 cols each
__global__ void k_state_gru(const float* __restrict__ Ws, const float* __restrict__ Us,
                            const float* __restrict__ bsin, const float* __restrict__ bsrec) {
    int tid = threadIdx.x;
    int g = blockIdx.x * 8 + (tid >> 4);
    int j = tid & 15;
    float xz = bsin[j], xr = bsin[16+j], xh = bsin[32+j];
    float hz = bsrec[j], hr = bsrec[16+j], hh = bsrec[32+j];
    for (int c = 0; c < 80; c++) {
        float v = (c < 32) ? g_asum[g*ATOMF + c]
                : (c < 64) ? g_esum[g*EDGEF + (c-32)]
                           : g_s[g*STATEF + (c-64)];
        xz += v*Ws[c*48 + j]; xr += v*Ws[c*48 + 16 + j]; xh += v*Ws[c*48 + 32 + j];
    }
    float h = g_s[g*STATEF + j];
    for (int c = 0; c < 16; c++) {
        float v = g_s[g*STATEF + c];
        hz += v*Us[c*48 + j]; hr += v*Us[c*48 + 16 + j]; hh += v*Us[c*48 + 32 + j];
    }
    float z = sigm(xz + hz);
    float r = sigm(xr + hr);
    float hc = tanhf(xh + r*hh);
    float out = z*h + (1.f - z)*hc;
    __syncthreads();            // all reads of g_s for this block's graphs complete
    g_s[g*STATEF + j] = out;
}

// ---------------- writeout: (a, e, s) flattened ----------------
__global__ void k_out(float* __restrict__ out) {
    int i = blockIdx.x * blockDim.x + threadIdx.x;
    const int na = NN*ATOMF, ne = EE*EDGEF, ns = GG*STATEF;
    if (i < na) { out[i] = g_a[i]; return; }
    i -= na;
    if (i < ne) { out[NN*ATOMF + i] = g_e[i]; return; }
    i -= ne;
    if (i < ns) out[NN*ATOMF + EE*EDGEF + i] = g_s[i];
}

// ---------------- launch ----------------
extern "C" void kernel_launch(void* const* d_in, const int* in_sizes, int n_in,
                              void* d_out, int out_size) {
    const float* a0    = (const float*)d_in[0];
    const float* e0    = (const float*)d_in[1];
    const float* s0    = (const float*)d_in[2];
    const int*   pair  = (const int*)d_in[3];
    const int*   agi   = (const int*)d_in[4];
    const int*   bgi   = (const int*)d_in[5];
    const float* Kmat  = (const float*)d_in[6];
    const float* bias  = (const float*)d_in[7];
    const float* We    = (const float*)d_in[8];
    const float* Ue    = (const float*)d_in[9];
    const float* bein  = (const float*)d_in[10];
    const float* berec = (const float*)d_in[11];
    const float* Wn    = (const float*)d_in[12];
    const float* Un    = (const float*)d_in[13];
    const float* bnin  = (const float*)d_in[14];
    const float* bnrec = (const float*)d_in[15];
    const float* Ws    = (const float*)d_in[16];
    const float* Us    = (const float*)d_in[17];
    const float* bsin  = (const float*)d_in[18];
    const float* bsrec = (const float*)d_in[19];

    const int eg_smem = (112*96 + 32*96 + 8*4*112) * (int)sizeof(float);  // 69632 B
    cudaFuncSetAttribute(k_edge_gru, cudaFuncAttributeMaxDynamicSharedMemorySize, eg_smem);

    int initN = NN*ATOMF + EE*EDGEF + GG*STATEF + CDIM*DD;
    k_init<<<(initN + 255)/256, 256>>>(a0, e0, s0, Kmat, bias);

    for (int step = 0; step < 2; step++) {
        int zN = NN*DD + GG*ATOMF + GG*EDGEF;
        k_zero<<<(zN + 255)/256, 256>>>();
        k_edge_gru<<<EE/32, 256, eg_smem>>>(We, Ue, bein, berec, pair, bgi);
        k_einsum<<<EE/TE, 256>>>(pair, agi);
        k_node_gru<<<(NN + 31)/32, 256>>>(Wn, Un, bnin, bnrec, agi);
        k_state_gru<<<GG/8, 128>>>(Ws, Us, bsin, bsrec);
    }

    int oN = NN*ATOMF + EE*EDGEF + GG*STATEF;
    k_out<<<(oN + 255)/256, 256>>>((float*)d_out);
}